// round 1
// baseline (speedup 1.0000x reference)
#include <cuda_runtime.h>
#include <math.h>

// Problem constants
#define kB   4
#define kNH  12
#define kHD  64
#define kSQ  1024          // H*W
#define kBH  48            // B * NH
#define kC   768
#define kN3  2304          // 3*C
#define kM   4096          // B * S

// ---------------- scratch (static device globals; no allocation) -------------
__device__ __align__(16) float g_Q[kBH * kSQ * kHD];     // 12.6 MB
__device__ __align__(16) float g_K[kBH * kSQ * kHD];
__device__ __align__(16) float g_V[kBH * kSQ * kHD];
__device__ __align__(16) float g_relh[kBH * kSQ * 32];   // 6.3 MB
__device__ __align__(16) float g_relw[kBH * kSQ * 32];
__device__ __align__(16) float g_att[kM * kC];           // 12.6 MB, (B,S,C) layout

// ---------------- 128x128x8 register-blocked SGEMM ---------------------------
// mode 0: C = A @ B, scatter into g_Q/g_K/g_V ([bh][s][hd] layout)
// mode 1: C = g_att @ B + bias -> out
__global__ __launch_bounds__(256, 2)
void sgemm128(const float* __restrict__ A, const float* __restrict__ Bm,
              const float* __restrict__ bias, float* __restrict__ out,
              int M, int N, int K, int mode)
{
    __shared__ float As[8][128];
    __shared__ float Bs[8][128];

    const int tid = threadIdx.x;
    const int bx = blockIdx.x, by = blockIdx.y;

    const int rowA = tid >> 1;            // 0..127
    const int colA = (tid & 1) * 4;       // 0 or 4
    const int rowB = tid >> 5;            // 0..7
    const int colB = (tid & 31) * 4;      // 0..124
    const int tr = tid >> 4;              // 0..15
    const int tc = tid & 15;              // 0..15

    const float* Ap = (mode == 0) ? A : g_att;

    float acc[8][8];
#pragma unroll
    for (int i = 0; i < 8; i++)
#pragma unroll
        for (int j = 0; j < 8; j++) acc[i][j] = 0.0f;

    const float* Abase = Ap + (size_t)(by * 128) * K;
    const float* Bbase = Bm + bx * 128;

    for (int k0 = 0; k0 < K; k0 += 8) {
        float4 a4 = *(const float4*)(Abase + (size_t)rowA * K + k0 + colA);
        As[colA + 0][rowA] = a4.x;
        As[colA + 1][rowA] = a4.y;
        As[colA + 2][rowA] = a4.z;
        As[colA + 3][rowA] = a4.w;
        float4 b4 = *(const float4*)(Bbase + (size_t)(k0 + rowB) * N + colB);
        *(float4*)&Bs[rowB][colB] = b4;
        __syncthreads();

#pragma unroll
        for (int k = 0; k < 8; k++) {
            float rm[8], rn[8];
#pragma unroll
            for (int i = 0; i < 8; i++) rm[i] = As[k][tr * 8 + i];
#pragma unroll
            for (int j = 0; j < 8; j++) rn[j] = Bs[k][tc * 8 + j];
#pragma unroll
            for (int i = 0; i < 8; i++)
#pragma unroll
                for (int j = 0; j < 8; j++)
                    acc[i][j] += rm[i] * rn[j];
        }
        __syncthreads();
    }

    const int gm0 = by * 128 + tr * 8;
    const int gn0 = bx * 128 + tc * 8;

    if (mode == 0) {
        // scatter into Q/K/V: col = which*768 + head*64 + d
        const int which = gn0 / kC;
        const int cc    = gn0 % kC;
        const int head  = cc / kHD;
        const int d0    = cc % kHD;          // multiple of 8 -> stays in one head
        float* dst = (which == 0) ? g_Q : ((which == 1) ? g_K : g_V);
#pragma unroll
        for (int i = 0; i < 8; i++) {
            const int gm = gm0 + i;
            const int b = gm >> 10, s = gm & 1023;
            float* p = dst + (((size_t)(b * kNH + head) * kSQ + s) * kHD + d0);
#pragma unroll
            for (int j = 0; j < 8; j += 4) {
                float4 v = make_float4(acc[i][j], acc[i][j+1], acc[i][j+2], acc[i][j+3]);
                *(float4*)(p + j) = v;
            }
        }
    } else {
        float bv[8];
#pragma unroll
        for (int j = 0; j < 8; j++) bv[j] = bias[gn0 + j];
#pragma unroll
        for (int i = 0; i < 8; i++) {
            float* p = out + (size_t)(gm0 + i) * N + gn0;
#pragma unroll
            for (int j = 0; j < 8; j += 4) {
                float4 v = make_float4(acc[i][j] + bv[j], acc[i][j+1] + bv[j+1],
                                       acc[i][j+2] + bv[j+2], acc[i][j+3] + bv[j+3]);
                *(float4*)(p + j) = v;
            }
        }
    }
}

// ---------------- relative position bias GEMVs -------------------------------
// rel_h[bh, s, kh] = sum_d Q[bh,s,d] * rel_pos_h[h - kh + 31, d]   (h = s/32)
// rel_w[bh, s, kw] = sum_d Q[bh,s,d] * rel_pos_w[w - kw + 31, d]   (w = s%32)
__global__ __launch_bounds__(64)
void relbias_kernel(const float* __restrict__ rph, const float* __restrict__ rpw)
{
    const int bh = blockIdx.y;
    const int s  = blockIdx.x;
    const int h = s >> 5, w = s & 31;
    const int t = threadIdx.x;

    __shared__ float q[64];
    q[t] = g_Q[((size_t)bh * kSQ + s) * kHD + t];
    __syncthreads();

    const float* tab;
    float* dst;
    if (t < 32) {
        const int r = h - t + 31;
        tab = rph + r * kHD;
        dst = g_relh + ((size_t)bh * kSQ + s) * 32 + t;
    } else {
        const int kk = t - 32;
        const int r = w - kk + 31;
        tab = rpw + r * kHD;
        dst = g_relw + ((size_t)bh * kSQ + s) * 32 + kk;
    }

    float sum = 0.0f;
#pragma unroll
    for (int d = 0; d < 64; d += 4) {
        float4 tv = *(const float4*)(tab + d);
        sum += q[d] * tv.x + q[d + 1] * tv.y + q[d + 2] * tv.z + q[d + 3] * tv.w;
    }
    *dst = sum;
}

// ---------------- fused flash attention (one query per thread) ---------------
// Block: 128 threads = 128 queries of one (bh). Loop over 32 key tiles of 32.
// A 32-key tile has constant kh = tile -> bias = rel_h scalar + rel_w[kw] regs.
__global__ __launch_bounds__(128, 2)
void flash_kernel()
{
    const int bh = blockIdx.y;
    const int q0 = blockIdx.x * 128 + threadIdx.x;
    const int tid = threadIdx.x;

    __shared__ float Ks[32][64];
    __shared__ float Vs[32][64];

    // load q row into registers
    float qreg[64];
    {
        const float* qp = g_Q + ((size_t)bh * kSQ + q0) * kHD;
#pragma unroll
        for (int d = 0; d < 64; d += 4) {
            float4 v = *(const float4*)(qp + d);
            qreg[d] = v.x; qreg[d+1] = v.y; qreg[d+2] = v.z; qreg[d+3] = v.w;
        }
    }
    // rel_w row for this query (kw = 0..31)
    float rw[32];
    {
        const float* rwp = g_relw + ((size_t)bh * kSQ + q0) * 32;
#pragma unroll
        for (int j = 0; j < 32; j += 4) {
            float4 v = *(const float4*)(rwp + j);
            rw[j] = v.x; rw[j+1] = v.y; rw[j+2] = v.z; rw[j+3] = v.w;
        }
    }
    const float* rhp = g_relh + ((size_t)bh * kSQ + q0) * 32;

    float acc[64];
#pragma unroll
    for (int d = 0; d < 64; d++) acc[d] = 0.0f;
    float m = -INFINITY;
    float l = 0.0f;

    const float4* Kb4 = (const float4*)(g_K + (size_t)bh * kSQ * kHD);
    const float4* Vb4 = (const float4*)(g_V + (size_t)bh * kSQ * kHD);
    float4* Ks4 = (float4*)&Ks[0][0];
    float4* Vs4 = (float4*)&Vs[0][0];

    for (int tile = 0; tile < 32; tile++) {
        __syncthreads();
        // load 32x64 K tile + V tile (512 float4 each, 128 threads x 4)
#pragma unroll
        for (int i = 0; i < 4; i++) {
            Ks4[tid + i * 128] = Kb4[tile * 512 + tid + i * 128];
            Vs4[tid + i * 128] = Vb4[tile * 512 + tid + i * 128];
        }
        __syncthreads();

        const float bias_h = __ldg(rhp + tile);

        float p[32];
        float mt = m;
#pragma unroll
        for (int j = 0; j < 32; j++) {
            float s0 = 0.0f;
#pragma unroll
            for (int d = 0; d < 64; d++) s0 += qreg[d] * Ks[j][d];
            s0 = s0 * 0.125f + bias_h + rw[j];
            p[j] = s0;
            mt = fmaxf(mt, s0);
        }
        const float alpha = __expf(m - mt);
        m = mt;
        float ls = 0.0f;
#pragma unroll
        for (int j = 0; j < 32; j++) {
            p[j] = __expf(p[j] - mt);
            ls += p[j];
        }
        l = l * alpha + ls;
#pragma unroll
        for (int d = 0; d < 64; d++) acc[d] *= alpha;
#pragma unroll
        for (int j = 0; j < 32; j++) {
#pragma unroll
            for (int d = 0; d < 64; d++) acc[d] += p[j] * Vs[j][d];
        }
    }

    const float inv = 1.0f / l;
    const int b = bh / kNH, head = bh % kNH;
    float* op = g_att + ((size_t)(b * kSQ + q0)) * kC + head * kHD;
#pragma unroll
    for (int d = 0; d < 64; d += 4) {
        float4 v = make_float4(acc[d] * inv, acc[d+1] * inv, acc[d+2] * inv, acc[d+3] * inv);
        *(float4*)(op + d) = v;
    }
}

// ---------------- launch ------------------------------------------------------
extern "C" void kernel_launch(void* const* d_in, const int* in_sizes, int n_in,
                              void* d_out, int out_size)
{
    const float* x     = (const float*)d_in[0];   // (4,32,32,768)
    const float* Wqkv  = (const float*)d_in[1];   // (768,2304)
    const float* Wproj = (const float*)d_in[2];   // (768,768)
    const float* bproj = (const float*)d_in[3];   // (768,)
    const float* rph   = (const float*)d_in[4];   // (63,64)
    const float* rpw   = (const float*)d_in[5];   // (63,64)
    float* out = (float*)d_out;

    // 1) qkv = x @ Wqkv, scattered into Q/K/V [bh][s][hd]
    sgemm128<<<dim3(kN3 / 128, kM / 128), 256>>>(x, Wqkv, nullptr, nullptr,
                                                 kM, kN3, kC, 0);
    // 2) decomposed relative position bias
    relbias_kernel<<<dim3(kSQ, kBH), 64>>>(rph, rpw);
    // 3) fused attention (scores + bias + softmax + PV), output (B,S,C)
    flash_kernel<<<dim3(kSQ / 128, kBH), 128>>>();
    // 4) out = att @ Wproj + bproj
    sgemm128<<<dim3(kC / 128, kM / 128), 256>>>(nullptr, Wproj, bproj, out,
                                                kM, kC, kC, 1);
}